// round 15
// baseline (speedup 1.0000x reference)
#include <cuda_runtime.h>
#include <cuda_bf16.h>
#include <cstdint>
#include <math.h>

#define BB 2
#define SS 2048
#define DM 768
#define NH 12
#define DH 64
#define MROWS (BB*SS)   // 4096
#define SW32 (SS/32)    // 64 mask words per row

#define BLK 64          // proj block tile M and N
#define BK  32          // proj block tile K
#define SA  40          // proj smem row stride (bf16)
#define NKS (DM/BK)     // 24 k-steps

#define TQ 64           // flash q-tile rows (4 warps x 16 rows)
#define TK 64           // flash k-tile rows
#define LDQ 72          // flash smem row stride (bf16)
#define PL (TQ*LDQ)     // flash plane elems

// ---- scratch (device globals; no allocation allowed) ----
__device__ __nv_bfloat16 g_xq_h[(size_t)MROWS*DM], g_xq_l[(size_t)MROWS*DM];
__device__ __nv_bfloat16 g_xk_h[(size_t)MROWS*DM], g_xk_l[(size_t)MROWS*DM];
__device__ __nv_bfloat16 g_xv_h[(size_t)MROWS*DM], g_xv_l[(size_t)MROWS*DM];
__device__ __nv_bfloat16 g_wq_h[(size_t)DM*DM], g_wq_l[(size_t)DM*DM];
__device__ __nv_bfloat16 g_wk_h[(size_t)DM*DM], g_wk_l[(size_t)DM*DM];
__device__ __nv_bfloat16 g_wv_h[(size_t)DM*DM], g_wv_l[(size_t)DM*DM];
__device__ __nv_bfloat16 g_wo_h[(size_t)DM*DM], g_wo_l[(size_t)DM*DM];
__device__ __nv_bfloat16 g_qh_h[(size_t)BB*NH*SS*DH], g_qh_l[(size_t)BB*NH*SS*DH];
__device__ __nv_bfloat16 g_kh_h[(size_t)BB*NH*SS*DH], g_kh_l[(size_t)BB*NH*SS*DH];
__device__ __nv_bfloat16 g_vh_h[(size_t)BB*NH*SS*DH], g_vh_l[(size_t)BB*NH*SS*DH];
__device__ __nv_bfloat16 g_ao_h[(size_t)MROWS*DM], g_ao_l[(size_t)MROWS*DM];
__device__ uint32_t g_mpack[(size_t)BB*SS*SW32];   // bit-packed mask

// ------------------------------------------------------------
// helpers
// ------------------------------------------------------------
__device__ __forceinline__ uint32_t bf2pack(__nv_bfloat16 a, __nv_bfloat16 b) {
    __nv_bfloat162 v; v.x = a; v.y = b;
    return *reinterpret_cast<uint32_t*>(&v);
}
__device__ __forceinline__ void split_pack(float x, float y, uint32_t& h, uint32_t& l) {
    __nv_bfloat16 hx = __float2bfloat16(x), hy = __float2bfloat16(y);
    h = bf2pack(hx, hy);
    l = bf2pack(__float2bfloat16(x - __bfloat162float(hx)),
                __float2bfloat16(y - __bfloat162float(hy)));
}
__device__ __forceinline__ void mma_bf16(float c[4],
                                         uint32_t a0, uint32_t a1, uint32_t a2, uint32_t a3,
                                         uint32_t b0, uint32_t b1) {
    asm volatile(
        "mma.sync.aligned.m16n8k16.row.col.f32.bf16.bf16.f32 "
        "{%0,%1,%2,%3},{%4,%5,%6,%7},{%8,%9},{%0,%1,%2,%3};"
        : "+f"(c[0]), "+f"(c[1]), "+f"(c[2]), "+f"(c[3])
        : "r"(a0), "r"(a1), "r"(a2), "r"(a3), "r"(b0), "r"(b1));
}
__device__ __forceinline__ uint32_t sptr(const void* p) {
    return (uint32_t)__cvta_generic_to_shared(p);
}
__device__ __forceinline__ void ldsm_x4(uint32_t& r0, uint32_t& r1, uint32_t& r2, uint32_t& r3, uint32_t a) {
    asm volatile("ldmatrix.sync.aligned.m8n8.x4.shared.b16 {%0,%1,%2,%3}, [%4];"
                 : "=r"(r0), "=r"(r1), "=r"(r2), "=r"(r3) : "r"(a));
}
__device__ __forceinline__ void ldsm_x4_trans(uint32_t& r0, uint32_t& r1, uint32_t& r2, uint32_t& r3, uint32_t a) {
    asm volatile("ldmatrix.sync.aligned.m8n8.x4.trans.shared.b16 {%0,%1,%2,%3}, [%4];"
                 : "=r"(r0), "=r"(r1), "=r"(r2), "=r"(r3) : "r"(a));
}
__device__ __forceinline__ void ldsm_x2(uint32_t& r0, uint32_t& r1, uint32_t a) {
    asm volatile("ldmatrix.sync.aligned.m8n8.x2.shared.b16 {%0,%1}, [%2];"
                 : "=r"(r0), "=r"(r1) : "r"(a));
}
__device__ __forceinline__ void cp16(uint32_t s, const void* g) {
    asm volatile("cp.async.cg.shared.global [%0], [%1], 16;" :: "r"(s), "l"(g));
}
__device__ __forceinline__ void cp_commit() { asm volatile("cp.async.commit_group;"); }
__device__ __forceinline__ void cp_wait0()  { asm volatile("cp.async.wait_group 0;"); }
__device__ __forceinline__ void cp_wait1()  { asm volatile("cp.async.wait_group 1;"); }

// ============================================================
// mask bit-pack: 32 ints -> 1 word via ballot
// ============================================================
__global__ __launch_bounds__(256)
void pack_mask(const int* __restrict__ M) {
    size_t i = (size_t)blockIdx.x * blockDim.x + threadIdx.x;
    uint32_t w = __ballot_sync(0xffffffffu, M[i] != 0);
    if ((threadIdx.x & 31) == 0) g_mpack[i >> 5] = w;
}

// ============================================================
// fused split: up to 4 tensors, selected by blockIdx.y
// ============================================================
struct SplitArgs {
    const float* x[4];
    __nv_bfloat16* h[4];
    __nv_bfloat16* l[4];
};

__global__ __launch_bounds__(256)
void split_multi(SplitArgs S, int n) {
    const float* x = S.x[blockIdx.y];
    __nv_bfloat16* h = S.h[blockIdx.y];
    __nv_bfloat16* l = S.l[blockIdx.y];
    int i = (blockIdx.x * blockDim.x + threadIdx.x) * 4;
    if (i >= n) return;
    float4 v = *(const float4*)&x[i];
    uint32_t h0, l0, h1, l1;
    split_pack(v.x, v.y, h0, l0);
    split_pack(v.z, v.w, h1, l1);
    uint32_t* H = (uint32_t*)h; uint32_t* L = (uint32_t*)l;
    H[(i>>1)  ] = h0; H[(i>>1)+1] = h1;
    L[(i>>1)  ] = l0; L[(i>>1)+1] = l1;
}

// ============================================================
// Projection GEMM: 64x64 tile, 128 threads, DOUBLE-BUFFERED
// cp.async (prefetch k+1 under wait_group 1), bf16x3.
// smem 40 KB static -> ~5 CTAs/SM.
// ============================================================
struct ProjArgs {
    const __nv_bfloat16 *Agh, *Agl, *Bgh, *Bgl;
    const float* bias;
    float scale;
    __nv_bfloat16 *Oh, *Ol;   // MODE 0 outputs
    float* Of;                // MODE 1 output
};
struct Proj3 { ProjArgs p[3]; };

template<int MODE>
__device__ __forceinline__ void proj_body(const ProjArgs& A) {
    __shared__ __nv_bfloat16 Ah[2][BLK*SA], Al[2][BLK*SA];
    __shared__ __nv_bfloat16 Bh[2][BLK*SA], Bl[2][BLK*SA];

    const int tid = threadIdx.x, lane = tid & 31, warp = tid >> 5;
    const int g = lane >> 2, t = lane & 3, l15 = lane & 15;
    const int wm = warp >> 1, wn = warp & 1;
    const size_t arow0 = (size_t)blockIdx.y * BLK;
    const size_t brow0 = (size_t)blockIdx.x * BLK;
    const int srow = tid >> 1, scb = (tid & 1) * 16;

    float acc[2][4][4] = {};

    // prologue: stage k-step 0 into buffer 0
    #pragma unroll
    for (int j = 0; j < 2; j++) {
        int c = scb + 8*j;
        cp16(sptr(&Ah[0][srow*SA + c]), &A.Agh[(arow0+srow)*DM + c]);
        cp16(sptr(&Al[0][srow*SA + c]), &A.Agl[(arow0+srow)*DM + c]);
        cp16(sptr(&Bh[0][srow*SA + c]), &A.Bgh[(brow0+srow)*DM + c]);
        cp16(sptr(&Bl[0][srow*SA + c]), &A.Bgl[(brow0+srow)*DM + c]);
    }
    cp_commit();

    for (int ks = 0; ks < NKS; ks++) {
        const int cur = ks & 1;
        if (ks + 1 < NKS) {
            const int k0 = (ks + 1) * BK;
            #pragma unroll
            for (int j = 0; j < 2; j++) {
                int c = scb + 8*j;
                cp16(sptr(&Ah[cur^1][srow*SA + c]), &A.Agh[(arow0+srow)*DM + k0 + c]);
                cp16(sptr(&Al[cur^1][srow*SA + c]), &A.Agl[(arow0+srow)*DM + k0 + c]);
                cp16(sptr(&Bh[cur^1][srow*SA + c]), &A.Bgh[(brow0+srow)*DM + k0 + c]);
                cp16(sptr(&Bl[cur^1][srow*SA + c]), &A.Bgl[(brow0+srow)*DM + k0 + c]);
            }
            cp_commit();
            cp_wait1();
        } else {
            cp_wait0();
        }
        __syncthreads();

        #pragma unroll
        for (int kc = 0; kc < BK; kc += 16) {
            uint32_t ah[2][4], al[2][4];
            #pragma unroll
            for (int i = 0; i < 2; i++) {
                int ar = wm*32 + i*16 + l15;
                int ac = kc + ((lane >> 4) << 3);
                ldsm_x4(ah[i][0], ah[i][1], ah[i][2], ah[i][3], sptr(&Ah[cur][ar*SA + ac]));
                ldsm_x4(al[i][0], al[i][1], al[i][2], al[i][3], sptr(&Al[cur][ar*SA + ac]));
            }
            #pragma unroll
            for (int j = 0; j < 4; j++) {
                int br = wn*32 + j*8 + (l15 & 7);
                int bc = kc + ((l15 >> 3) << 3);
                uint32_t bh0, bh1, bl0, bl1;
                ldsm_x2(bh0, bh1, sptr(&Bh[cur][br*SA + bc]));
                ldsm_x2(bl0, bl1, sptr(&Bl[cur][br*SA + bc]));
                #pragma unroll
                for (int i = 0; i < 2; i++) {
                    mma_bf16(acc[i][j], ah[i][0],ah[i][1],ah[i][2],ah[i][3], bh0, bh1);
                    mma_bf16(acc[i][j], ah[i][0],ah[i][1],ah[i][2],ah[i][3], bl0, bl1);
                    mma_bf16(acc[i][j], al[i][0],al[i][1],al[i][2],al[i][3], bh0, bh1);
                }
            }
        }
        __syncthreads();   // all warps done with cur before ks+2 restages it
    }

    #pragma unroll
    for (int i = 0; i < 2; i++) {
        #pragma unroll
        for (int rr = 0; rr < 2; rr++) {
            int r = (int)arow0 + wm*32 + i*16 + g + rr*8;
            #pragma unroll
            for (int j = 0; j < 4; j++) {
                int c = (int)brow0 + wn*32 + j*8 + 2*t;
                float v0 = (acc[i][j][rr*2  ] + A.bias[c  ]) * A.scale;
                float v1 = (acc[i][j][rr*2+1] + A.bias[c+1]) * A.scale;
                if (MODE == 0) {
                    int b_ = r / SS, s_ = r % SS;
                    int h_ = c / DH, d_ = c % DH;
                    size_t idx = ((size_t)(b_*NH + h_)*SS + s_)*DH + d_;
                    uint32_t ph, pl;
                    split_pack(v0, v1, ph, pl);
                    *(uint32_t*)&A.Oh[idx] = ph;
                    *(uint32_t*)&A.Ol[idx] = pl;
                } else {
                    float2 o; o.x = v0; o.y = v1;
                    *(float2*)&A.Of[(size_t)r*DM + c] = o;
                }
            }
        }
    }
}

// merged QKV projection: blockIdx.z selects {Q,K,V}
__global__ __launch_bounds__(128)
void proj_qkv(Proj3 P) {
    proj_body<0>(P.p[blockIdx.z]);
}

// single projection (WO, fp32 out)
__global__ __launch_bounds__(128)
void proj_out(ProjArgs A) {
    proj_body<1>(A);
}

// ============================================================
// FLASH ATTENTION (R14-proven): flat softmax, pre-loaded mask
// bits, Q staged in smem. 6 planes = 54 KB; 128 thr; 4 CTAs/SM.
// ============================================================
__global__ __launch_bounds__(128, 4)
void flash_attn() {
    extern __shared__ __nv_bfloat16 dsm[];
    __nv_bfloat16* Qh = dsm;
    __nv_bfloat16* Ql = dsm + PL;
    __nv_bfloat16* Kh = dsm + 2*PL;
    __nv_bfloat16* Kl = dsm + 3*PL;
    __nv_bfloat16* Vh = dsm + 4*PL;
    __nv_bfloat16* Vl = dsm + 5*PL;

    const int bh = blockIdx.y;
    const int b_ = bh / NH, h_ = bh % NH;
    const int q0 = blockIdx.x * TQ;
    const size_t qoff = ((size_t)bh*SS + q0)*DH;
    const size_t koff0 = (size_t)bh*SS*DH;
    const uint32_t* MP = g_mpack + (size_t)b_*SS*SW32;

    const int tid = threadIdx.x, lane = tid & 31, warp = tid >> 5;
    const int g = lane >> 2, t = lane & 3, l15 = lane & 15;
    const int sr = tid >> 1;
    const int sc0 = (tid & 1) * 32;

    #pragma unroll
    for (int j = 0; j < 4; j++) {
        int c = sc0 + 8*j;
        cp16(sptr(&Qh[sr*LDQ + c]), &g_qh_h[qoff + (size_t)sr*DH + c]);
        cp16(sptr(&Ql[sr*LDQ + c]), &g_qh_l[qoff + (size_t)sr*DH + c]);
    }
    cp_commit();

    float O[8][4] = {};
    float l0 = 0.f, l1 = 0.f;

    const int rg0 = q0 + warp*16 + g;
    const int rg1 = rg0 + 8;

    for (int kt = 0; kt < SS/TK; kt++) {
        __syncthreads();
        const size_t koff = koff0 + (size_t)kt*TK*DH;
        #pragma unroll
        for (int j = 0; j < 4; j++) {
            int c = sc0 + 8*j;
            cp16(sptr(&Kh[sr*LDQ + c]), &g_kh_h[koff + (size_t)sr*DH + c]);
            cp16(sptr(&Kl[sr*LDQ + c]), &g_kh_l[koff + (size_t)sr*DH + c]);
            cp16(sptr(&Vh[sr*LDQ + c]), &g_vh_h[koff + (size_t)sr*DH + c]);
            cp16(sptr(&Vl[sr*LDQ + c]), &g_vh_l[koff + (size_t)sr*DH + c]);
        }
        cp_commit();

        uint2 mw0 = *(const uint2*)&MP[(size_t)rg0*SW32 + kt*2];
        uint2 mw1 = *(const uint2*)&MP[(size_t)rg1*SW32 + kt*2];

        cp_wait0();
        __syncthreads();

        float S[8][4] = {};
        #pragma unroll
        for (int kc = 0; kc < 4; kc++) {
            uint32_t qhf[4], qlf[4];
            {
                int ar = warp*16 + l15;
                int ac = kc*16 + ((lane >> 4) << 3);
                ldsm_x4(qhf[0], qhf[1], qhf[2], qhf[3], sptr(&Qh[ar*LDQ + ac]));
                ldsm_x4(qlf[0], qlf[1], qlf[2], qlf[3], sptr(&Ql[ar*LDQ + ac]));
            }
            #pragma unroll
            for (int jp = 0; jp < 4; jp++) {
                int nr = 16*jp + ((lane >> 4) << 3) + (lane & 7);
                int ncol = kc*16 + (((lane >> 3) & 1) << 3);
                uint32_t bh0, bh1, bh2, bh3, bl0, bl1, bl2, bl3;
                ldsm_x4(bh0, bh1, bh2, bh3, sptr(&Kh[nr*LDQ + ncol]));
                ldsm_x4(bl0, bl1, bl2, bl3, sptr(&Kl[nr*LDQ + ncol]));
                mma_bf16(S[2*jp  ], qhf[0],qhf[1],qhf[2],qhf[3], bh0, bh1);
                mma_bf16(S[2*jp  ], qhf[0],qhf[1],qhf[2],qhf[3], bl0, bl1);
                mma_bf16(S[2*jp  ], qlf[0],qlf[1],qlf[2],qlf[3], bh0, bh1);
                mma_bf16(S[2*jp+1], qhf[0],qhf[1],qhf[2],qhf[3], bh2, bh3);
                mma_bf16(S[2*jp+1], qhf[0],qhf[1],qhf[2],qhf[3], bl2, bl3);
                mma_bf16(S[2*jp+1], qlf[0],qlf[1],qlf[2],qlf[3], bh2, bh3);
            }
        }

        #pragma unroll
        for (int j = 0; j < 8; j++) {
            uint32_t w0 = (j < 4) ? mw0.x : mw0.y;
            uint32_t w1 = (j < 4) ? mw1.x : mw1.y;
            int sh = (j & 3)*8 + 2*t;
            float e0 = __expf(S[j][0]);
            float e1 = __expf(S[j][1]);
            float e2 = __expf(S[j][2]);
            float e3 = __expf(S[j][3]);
            S[j][0] = ((w0 >> sh)     & 1u) ? e0 : 1.0f;
            S[j][1] = ((w0 >> (sh+1)) & 1u) ? e1 : 1.0f;
            S[j][2] = ((w1 >> sh)     & 1u) ? e2 : 1.0f;
            S[j][3] = ((w1 >> (sh+1)) & 1u) ? e3 : 1.0f;
            l0 += S[j][0] + S[j][1];
            l1 += S[j][2] + S[j][3];
        }

        #pragma unroll
        for (int kc = 0; kc < 4; kc++) {
            uint32_t ah[4], al[4];
            split_pack(S[2*kc  ][0], S[2*kc  ][1], ah[0], al[0]);
            split_pack(S[2*kc  ][2], S[2*kc  ][3], ah[1], al[1]);
            split_pack(S[2*kc+1][0], S[2*kc+1][1], ah[2], al[2]);
            split_pack(S[2*kc+1][2], S[2*kc+1][3], ah[3], al[3]);
            #pragma unroll
            for (int jp = 0; jp < 4; jp++) {
                int krow = kc*16 + (lane & 15);
                int ncol = 16*jp + ((lane >> 4) << 3);
                uint32_t bh0, bh1, bh2, bh3, bl0, bl1, bl2, bl3;
                ldsm_x4_trans(bh0, bh1, bh2, bh3, sptr(&Vh[krow*LDQ + ncol]));
                ldsm_x4_trans(bl0, bl1, bl2, bl3, sptr(&Vl[krow*LDQ + ncol]));
                mma_bf16(O[2*jp  ], ah[0],ah[1],ah[2],ah[3], bh0, bh1);
                mma_bf16(O[2*jp  ], ah[0],ah[1],ah[2],ah[3], bl0, bl1);
                mma_bf16(O[2*jp  ], al[0],al[1],al[2],al[3], bh0, bh1);
                mma_bf16(O[2*jp+1], ah[0],ah[1],ah[2],ah[3], bh2, bh3);
                mma_bf16(O[2*jp+1], ah[0],ah[1],ah[2],ah[3], bl2, bl3);
                mma_bf16(O[2*jp+1], al[0],al[1],al[2],al[3], bh2, bh3);
            }
        }
    }

    l0 += __shfl_xor_sync(0xffffffffu, l0, 1);
    l0 += __shfl_xor_sync(0xffffffffu, l0, 2);
    l1 += __shfl_xor_sync(0xffffffffu, l1, 1);
    l1 += __shfl_xor_sync(0xffffffffu, l1, 2);
    const float inv0 = 1.0f / l0, inv1 = 1.0f / l1;
    const size_t o0 = ((size_t)(b_*SS + rg0))*DM + h_*DH;
    const size_t o1 = ((size_t)(b_*SS + rg1))*DM + h_*DH;
    #pragma unroll
    for (int j = 0; j < 8; j++) {
        int c = j*8 + 2*t;
        uint32_t ph, pl;
        split_pack(O[j][0]*inv0, O[j][1]*inv0, ph, pl);
        *(uint32_t*)&g_ao_h[o0 + c] = ph;
        *(uint32_t*)&g_ao_l[o0 + c] = pl;
        split_pack(O[j][2]*inv1, O[j][3]*inv1, ph, pl);
        *(uint32_t*)&g_ao_h[o1 + c] = ph;
        *(uint32_t*)&g_ao_l[o1 + c] = pl;
    }
}

// ============================================================
extern "C" void kernel_launch(void* const* d_in, const int* in_sizes, int n_in,
                              void* d_out, int out_size) {
    const float* q    = (const float*)d_in[0];
    const float* k    = (const float*)d_in[1];
    const float* v    = (const float*)d_in[2];
    const int*   msk  = (const int*)  d_in[3];
    const float* WQ_w = (const float*)d_in[4];
    const float* WQ_b = (const float*)d_in[5];
    const float* WK_w = (const float*)d_in[6];
    const float* WK_b = (const float*)d_in[7];
    const float* WV_w = (const float*)d_in[8];
    const float* WV_b = (const float*)d_in[9];
    const float* WO_w = (const float*)d_in[10];
    const float* WO_b = (const float*)d_in[11];
    float* out = (float*)d_out;

    __nv_bfloat16 *xq_h,*xq_l,*xk_h,*xk_l,*xv_h,*xv_l;
    __nv_bfloat16 *wq_h,*wq_l,*wk_h,*wk_l,*wv_h,*wv_l,*wo_h,*wo_l;
    __nv_bfloat16 *qh_h,*qh_l,*kh_h,*kh_l,*vh_h,*vh_l,*ao_h,*ao_l;
    cudaGetSymbolAddress((void**)&xq_h, g_xq_h); cudaGetSymbolAddress((void**)&xq_l, g_xq_l);
    cudaGetSymbolAddress((void**)&xk_h, g_xk_h); cudaGetSymbolAddress((void**)&xk_l, g_xk_l);
    cudaGetSymbolAddress((void**)&xv_h, g_xv_h); cudaGetSymbolAddress((void**)&xv_l, g_xv_l);
    cudaGetSymbolAddress((void**)&wq_h, g_wq_h); cudaGetSymbolAddress((void**)&wq_l, g_wq_l);
    cudaGetSymbolAddress((void**)&wk_h, g_wk_h); cudaGetSymbolAddress((void**)&wk_l, g_wk_l);
    cudaGetSymbolAddress((void**)&wv_h, g_wv_h); cudaGetSymbolAddress((void**)&wv_l, g_wv_l);
    cudaGetSymbolAddress((void**)&wo_h, g_wo_h); cudaGetSymbolAddress((void**)&wo_l, g_wo_l);
    cudaGetSymbolAddress((void**)&qh_h, g_qh_h); cudaGetSymbolAddress((void**)&qh_l, g_qh_l);
    cudaGetSymbolAddress((void**)&kh_h, g_kh_h); cudaGetSymbolAddress((void**)&kh_l, g_kh_l);
    cudaGetSymbolAddress((void**)&vh_h, g_vh_h); cudaGetSymbolAddress((void**)&vh_l, g_vh_l);
    cudaGetSymbolAddress((void**)&ao_h, g_ao_h); cudaGetSymbolAddress((void**)&ao_l, g_ao_l);

    const int flash_smem = 6 * PL * (int)sizeof(__nv_bfloat16);   // 55296 B
    cudaFuncSetAttribute(flash_attn, cudaFuncAttributeMaxDynamicSharedMemorySize, flash_smem);

    const float qscale = 1.0f / 8.0f;   // 1/sqrt(64)

    // ---- mask bit-pack ----
    {
        size_t nm = (size_t)BB*SS*SS;
        pack_mask<<<(unsigned)(nm/256), 256>>>(msk);
    }

    // ---- fused splits: inputs (3) and weights (4) ----
    const int nx = MROWS*DM, nw = DM*DM;
    {
        SplitArgs si = {};
        si.x[0] = q;    si.h[0] = xq_h; si.l[0] = xq_l;
        si.x[1] = k;    si.h[1] = xk_h; si.l[1] = xk_l;
        si.x[2] = v;    si.h[2] = xv_h; si.l[2] = xv_l;
        dim3 gi((nx/4 + 255)/256, 3);
        split_multi<<<gi, 256>>>(si, nx);

        SplitArgs sw = {};
        sw.x[0] = WQ_w; sw.h[0] = wq_h; sw.l[0] = wq_l;
        sw.x[1] = WK_w; sw.h[1] = wk_h; sw.l[1] = wk_l;
        sw.x[2] = WV_w; sw.h[2] = wv_h; sw.l[2] = wv_l;
        sw.x[3] = WO_w; sw.h[3] = wo_h; sw.l[3] = wo_l;
        dim3 gw((nw/4 + 255)/256, 4);
        split_multi<<<gw, 256>>>(sw, nw);
    }

    // ---- merged QKV projections (grid.z = 3) ----
    {
        Proj3 P;
        P.p[0] = { xq_h, xq_l, wq_h, wq_l, WQ_b, qscale, qh_h, qh_l, nullptr };
        P.p[1] = { xk_h, xk_l, wk_h, wk_l, WK_b, 1.0f,   kh_h, kh_l, nullptr };
        P.p[2] = { xv_h, xv_l, wv_h, wv_l, WV_b, 1.0f,   vh_h, vh_l, nullptr };
        dim3 pg(DM/BLK, MROWS/BLK, 3);  // (12, 64, 3)
        proj_qkv<<<pg, 128>>>(P);
    }

    // ---- fused attention ----
    dim3 fg(SS/TQ, BB*NH);              // (32, 24)
    flash_attn<<<fg, 128, flash_smem>>>();

    // ---- output projection ----
    {
        ProjArgs A = { ao_h, ao_l, wo_h, wo_l, WO_b, 1.0f, nullptr, nullptr, out };
        dim3 pg(DM/BLK, MROWS/BLK);     // (12, 64)
        proj_out<<<pg, 128>>>(A);
    }
}

// round 16
// speedup vs baseline: 1.0320x; 1.0320x over previous
#include <cuda_runtime.h>
#include <cuda_bf16.h>
#include <cstdint>
#include <math.h>

#define BB 2
#define SS 2048
#define DM 768
#define NH 12
#define DH 64
#define MROWS (BB*SS)   // 4096
#define SW32 (SS/32)    // 64 mask words per row

#define BLK 64          // proj block tile M and N
#define BK  32          // proj block tile K
#define SA  40          // proj smem row stride (bf16)
#define NKS (DM/BK)     // 24 k-steps

#define TQ 64           // flash q-tile rows (4 warps x 16 rows)
#define TK 64           // flash k-tile rows
#define NKT (SS/TK)     // 32 k-tiles total
#define KSPLIT 2        // split-KV factor
#define LDQ 72          // flash smem row stride (bf16)
#define PL (TQ*LDQ)     // flash plane elems

// ---- scratch (device globals; no allocation allowed) ----
__device__ __nv_bfloat16 g_xq_h[(size_t)MROWS*DM], g_xq_l[(size_t)MROWS*DM];
__device__ __nv_bfloat16 g_xk_h[(size_t)MROWS*DM], g_xk_l[(size_t)MROWS*DM];
__device__ __nv_bfloat16 g_xv_h[(size_t)MROWS*DM], g_xv_l[(size_t)MROWS*DM];
__device__ __nv_bfloat16 g_wq_h[(size_t)DM*DM], g_wq_l[(size_t)DM*DM];
__device__ __nv_bfloat16 g_wk_h[(size_t)DM*DM], g_wk_l[(size_t)DM*DM];
__device__ __nv_bfloat16 g_wv_h[(size_t)DM*DM], g_wv_l[(size_t)DM*DM];
__device__ __nv_bfloat16 g_wo_h[(size_t)DM*DM], g_wo_l[(size_t)DM*DM];
__device__ __nv_bfloat16 g_qh_h[(size_t)BB*NH*SS*DH], g_qh_l[(size_t)BB*NH*SS*DH];
__device__ __nv_bfloat16 g_kh_h[(size_t)BB*NH*SS*DH], g_kh_l[(size_t)BB*NH*SS*DH];
__device__ __nv_bfloat16 g_vh_h[(size_t)BB*NH*SS*DH], g_vh_l[(size_t)BB*NH*SS*DH];
__device__ __nv_bfloat16 g_ao_h[(size_t)MROWS*DM], g_ao_l[(size_t)MROWS*DM];
__device__ uint32_t g_mpack[(size_t)BB*SS*SW32];          // bit-packed mask
__device__ float g_op[(size_t)KSPLIT*MROWS*DM];           // split-KV partial O (unnormalized)
__device__ float g_lp[(size_t)KSPLIT*BB*NH*SS];           // split-KV partial row sums

// ------------------------------------------------------------
// helpers
// ------------------------------------------------------------
__device__ __forceinline__ uint32_t bf2pack(__nv_bfloat16 a, __nv_bfloat16 b) {
    __nv_bfloat162 v; v.x = a; v.y = b;
    return *reinterpret_cast<uint32_t*>(&v);
}
__device__ __forceinline__ void split_pack(float x, float y, uint32_t& h, uint32_t& l) {
    __nv_bfloat16 hx = __float2bfloat16(x), hy = __float2bfloat16(y);
    h = bf2pack(hx, hy);
    l = bf2pack(__float2bfloat16(x - __bfloat162float(hx)),
                __float2bfloat16(y - __bfloat162float(hy)));
}
__device__ __forceinline__ void mma_bf16(float c[4],
                                         uint32_t a0, uint32_t a1, uint32_t a2, uint32_t a3,
                                         uint32_t b0, uint32_t b1) {
    asm volatile(
        "mma.sync.aligned.m16n8k16.row.col.f32.bf16.bf16.f32 "
        "{%0,%1,%2,%3},{%4,%5,%6,%7},{%8,%9},{%0,%1,%2,%3};"
        : "+f"(c[0]), "+f"(c[1]), "+f"(c[2]), "+f"(c[3])
        : "r"(a0), "r"(a1), "r"(a2), "r"(a3), "r"(b0), "r"(b1));
}
__device__ __forceinline__ uint32_t sptr(const void* p) {
    return (uint32_t)__cvta_generic_to_shared(p);
}
__device__ __forceinline__ void ldsm_x4(uint32_t& r0, uint32_t& r1, uint32_t& r2, uint32_t& r3, uint32_t a) {
    asm volatile("ldmatrix.sync.aligned.m8n8.x4.shared.b16 {%0,%1,%2,%3}, [%4];"
                 : "=r"(r0), "=r"(r1), "=r"(r2), "=r"(r3) : "r"(a));
}
__device__ __forceinline__ void ldsm_x4_trans(uint32_t& r0, uint32_t& r1, uint32_t& r2, uint32_t& r3, uint32_t a) {
    asm volatile("ldmatrix.sync.aligned.m8n8.x4.trans.shared.b16 {%0,%1,%2,%3}, [%4];"
                 : "=r"(r0), "=r"(r1), "=r"(r2), "=r"(r3) : "r"(a));
}
__device__ __forceinline__ void ldsm_x2(uint32_t& r0, uint32_t& r1, uint32_t a) {
    asm volatile("ldmatrix.sync.aligned.m8n8.x2.shared.b16 {%0,%1}, [%2];"
                 : "=r"(r0), "=r"(r1) : "r"(a));
}
__device__ __forceinline__ void cp16(uint32_t s, const void* g) {
    asm volatile("cp.async.cg.shared.global [%0], [%1], 16;" :: "r"(s), "l"(g));
}
__device__ __forceinline__ void cp_commit() { asm volatile("cp.async.commit_group;"); }
__device__ __forceinline__ void cp_wait0()  { asm volatile("cp.async.wait_group 0;"); }
__device__ __forceinline__ void cp_wait1()  { asm volatile("cp.async.wait_group 1;"); }

// ============================================================
// mask bit-pack: 32 ints -> 1 word via ballot
// ============================================================
__global__ __launch_bounds__(256)
void pack_mask(const int* __restrict__ M) {
    size_t i = (size_t)blockIdx.x * blockDim.x + threadIdx.x;
    uint32_t w = __ballot_sync(0xffffffffu, M[i] != 0);
    if ((threadIdx.x & 31) == 0) g_mpack[i >> 5] = w;
}

// ============================================================
// fused split: up to 4 tensors, selected by blockIdx.y
// ============================================================
struct SplitArgs {
    const float* x[4];
    __nv_bfloat16* h[4];
    __nv_bfloat16* l[4];
};

__global__ __launch_bounds__(256)
void split_multi(SplitArgs S, int n) {
    const float* x = S.x[blockIdx.y];
    __nv_bfloat16* h = S.h[blockIdx.y];
    __nv_bfloat16* l = S.l[blockIdx.y];
    int i = (blockIdx.x * blockDim.x + threadIdx.x) * 4;
    if (i >= n) return;
    float4 v = *(const float4*)&x[i];
    uint32_t h0, l0, h1, l1;
    split_pack(v.x, v.y, h0, l0);
    split_pack(v.z, v.w, h1, l1);
    uint32_t* H = (uint32_t*)h; uint32_t* L = (uint32_t*)l;
    H[(i>>1)  ] = h0; H[(i>>1)+1] = h1;
    L[(i>>1)  ] = l0; L[(i>>1)+1] = l1;
}

// ============================================================
// Projection GEMM (R15): 64x64 tile, 128 threads, double-buffered
// cp.async, bf16x3.
// ============================================================
struct ProjArgs {
    const __nv_bfloat16 *Agh, *Agl, *Bgh, *Bgl;
    const float* bias;
    float scale;
    __nv_bfloat16 *Oh, *Ol;   // MODE 0 outputs
    float* Of;                // MODE 1 output
};
struct Proj3 { ProjArgs p[3]; };

template<int MODE>
__device__ __forceinline__ void proj_body(const ProjArgs& A) {
    __shared__ __nv_bfloat16 Ah[2][BLK*SA], Al[2][BLK*SA];
    __shared__ __nv_bfloat16 Bh[2][BLK*SA], Bl[2][BLK*SA];

    const int tid = threadIdx.x, lane = tid & 31, warp = tid >> 5;
    const int g = lane >> 2, t = lane & 3, l15 = lane & 15;
    const int wm = warp >> 1, wn = warp & 1;
    const size_t arow0 = (size_t)blockIdx.y * BLK;
    const size_t brow0 = (size_t)blockIdx.x * BLK;
    const int srow = tid >> 1, scb = (tid & 1) * 16;

    float acc[2][4][4] = {};

    #pragma unroll
    for (int j = 0; j < 2; j++) {
        int c = scb + 8*j;
        cp16(sptr(&Ah[0][srow*SA + c]), &A.Agh[(arow0+srow)*DM + c]);
        cp16(sptr(&Al[0][srow*SA + c]), &A.Agl[(arow0+srow)*DM + c]);
        cp16(sptr(&Bh[0][srow*SA + c]), &A.Bgh[(brow0+srow)*DM + c]);
        cp16(sptr(&Bl[0][srow*SA + c]), &A.Bgl[(brow0+srow)*DM + c]);
    }
    cp_commit();

    for (int ks = 0; ks < NKS; ks++) {
        const int cur = ks & 1;
        if (ks + 1 < NKS) {
            const int k0 = (ks + 1) * BK;
            #pragma unroll
            for (int j = 0; j < 2; j++) {
                int c = scb + 8*j;
                cp16(sptr(&Ah[cur^1][srow*SA + c]), &A.Agh[(arow0+srow)*DM + k0 + c]);
                cp16(sptr(&Al[cur^1][srow*SA + c]), &A.Agl[(arow0+srow)*DM + k0 + c]);
                cp16(sptr(&Bh[cur^1][srow*SA + c]), &A.Bgh[(brow0+srow)*DM + k0 + c]);
                cp16(sptr(&Bl[cur^1][srow*SA + c]), &A.Bgl[(brow0+srow)*DM + k0 + c]);
            }
            cp_commit();
            cp_wait1();
        } else {
            cp_wait0();
        }
        __syncthreads();

        #pragma unroll
        for (int kc = 0; kc < BK; kc += 16) {
            uint32_t ah[2][4], al[2][4];
            #pragma unroll
            for (int i = 0; i < 2; i++) {
                int ar = wm*32 + i*16 + l15;
                int ac = kc + ((lane >> 4) << 3);
                ldsm_x4(ah[i][0], ah[i][1], ah[i][2], ah[i][3], sptr(&Ah[cur][ar*SA + ac]));
                ldsm_x4(al[i][0], al[i][1], al[i][2], al[i][3], sptr(&Al[cur][ar*SA + ac]));
            }
            #pragma unroll
            for (int j = 0; j < 4; j++) {
                int br = wn*32 + j*8 + (l15 & 7);
                int bc = kc + ((l15 >> 3) << 3);
                uint32_t bh0, bh1, bl0, bl1;
                ldsm_x2(bh0, bh1, sptr(&Bh[cur][br*SA + bc]));
                ldsm_x2(bl0, bl1, sptr(&Bl[cur][br*SA + bc]));
                #pragma unroll
                for (int i = 0; i < 2; i++) {
                    mma_bf16(acc[i][j], ah[i][0],ah[i][1],ah[i][2],ah[i][3], bh0, bh1);
                    mma_bf16(acc[i][j], ah[i][0],ah[i][1],ah[i][2],ah[i][3], bl0, bl1);
                    mma_bf16(acc[i][j], al[i][0],al[i][1],al[i][2],al[i][3], bh0, bh1);
                }
            }
        }
        __syncthreads();
    }

    #pragma unroll
    for (int i = 0; i < 2; i++) {
        #pragma unroll
        for (int rr = 0; rr < 2; rr++) {
            int r = (int)arow0 + wm*32 + i*16 + g + rr*8;
            #pragma unroll
            for (int j = 0; j < 4; j++) {
                int c = (int)brow0 + wn*32 + j*8 + 2*t;
                float v0 = (acc[i][j][rr*2  ] + A.bias[c  ]) * A.scale;
                float v1 = (acc[i][j][rr*2+1] + A.bias[c+1]) * A.scale;
                if (MODE == 0) {
                    int b_ = r / SS, s_ = r % SS;
                    int h_ = c / DH, d_ = c % DH;
                    size_t idx = ((size_t)(b_*NH + h_)*SS + s_)*DH + d_;
                    uint32_t ph, pl;
                    split_pack(v0, v1, ph, pl);
                    *(uint32_t*)&A.Oh[idx] = ph;
                    *(uint32_t*)&A.Ol[idx] = pl;
                } else {
                    float2 o; o.x = v0; o.y = v1;
                    *(float2*)&A.Of[(size_t)r*DM + c] = o;
                }
            }
        }
    }
}

__global__ __launch_bounds__(128)
void proj_qkv(Proj3 P) {
    proj_body<0>(P.p[blockIdx.z]);
}

__global__ __launch_bounds__(128)
void proj_out(ProjArgs A) {
    proj_body<1>(A);
}

// ============================================================
// FLASH ATTENTION, split-KV x2: flat softmax partials are exactly
// additive, so each z-half writes unnormalized fp32 O + row sum l.
// grid (SS/TQ, BB*NH, KSPLIT). 6 planes = 54 KB; 128 thr; 4 CTAs/SM.
// ============================================================
__global__ __launch_bounds__(128, 4)
void flash_attn() {
    extern __shared__ __nv_bfloat16 dsm[];
    __nv_bfloat16* Qh = dsm;
    __nv_bfloat16* Ql = dsm + PL;
    __nv_bfloat16* Kh = dsm + 2*PL;
    __nv_bfloat16* Kl = dsm + 3*PL;
    __nv_bfloat16* Vh = dsm + 4*PL;
    __nv_bfloat16* Vl = dsm + 5*PL;

    const int bh = blockIdx.y;
    const int zz = blockIdx.z;
    const int b_ = bh / NH, h_ = bh % NH;
    const int q0 = blockIdx.x * TQ;
    const size_t qoff = ((size_t)bh*SS + q0)*DH;
    const size_t koff0 = (size_t)bh*SS*DH;
    const uint32_t* MP = g_mpack + (size_t)b_*SS*SW32;

    const int tid = threadIdx.x, lane = tid & 31, warp = tid >> 5;
    const int g = lane >> 2, t = lane & 3, l15 = lane & 15;
    const int sr = tid >> 1;
    const int sc0 = (tid & 1) * 32;

    #pragma unroll
    for (int j = 0; j < 4; j++) {
        int c = sc0 + 8*j;
        cp16(sptr(&Qh[sr*LDQ + c]), &g_qh_h[qoff + (size_t)sr*DH + c]);
        cp16(sptr(&Ql[sr*LDQ + c]), &g_qh_l[qoff + (size_t)sr*DH + c]);
    }
    cp_commit();

    float O[8][4] = {};
    float l0 = 0.f, l1 = 0.f;

    const int rg0 = q0 + warp*16 + g;
    const int rg1 = rg0 + 8;

    const int kt0 = zz * (NKT/KSPLIT);
    const int kt1 = kt0 + (NKT/KSPLIT);

    for (int kt = kt0; kt < kt1; kt++) {
        __syncthreads();
        const size_t koff = koff0 + (size_t)kt*TK*DH;
        #pragma unroll
        for (int j = 0; j < 4; j++) {
            int c = sc0 + 8*j;
            cp16(sptr(&Kh[sr*LDQ + c]), &g_kh_h[koff + (size_t)sr*DH + c]);
            cp16(sptr(&Kl[sr*LDQ + c]), &g_kh_l[koff + (size_t)sr*DH + c]);
            cp16(sptr(&Vh[sr*LDQ + c]), &g_vh_h[koff + (size_t)sr*DH + c]);
            cp16(sptr(&Vl[sr*LDQ + c]), &g_vh_l[koff + (size_t)sr*DH + c]);
        }
        cp_commit();

        uint2 mw0 = *(const uint2*)&MP[(size_t)rg0*SW32 + kt*2];
        uint2 mw1 = *(const uint2*)&MP[(size_t)rg1*SW32 + kt*2];

        cp_wait0();
        __syncthreads();

        float S[8][4] = {};
        #pragma unroll
        for (int kc = 0; kc < 4; kc++) {
            uint32_t qhf[4], qlf[4];
            {
                int ar = warp*16 + l15;
                int ac = kc*16 + ((lane >> 4) << 3);
                ldsm_x4(qhf[0], qhf[1], qhf[2], qhf[3], sptr(&Qh[ar*LDQ + ac]));
                ldsm_x4(qlf[0], qlf[1], qlf[2], qlf[3], sptr(&Ql[ar*LDQ + ac]));
            }
            #pragma unroll
            for (int jp = 0; jp < 4; jp++) {
                int nr = 16*jp + ((lane >> 4) << 3) + (lane & 7);
                int ncol = kc*16 + (((lane >> 3) & 1) << 3);
                uint32_t bh0, bh1, bh2, bh3, bl0, bl1, bl2, bl3;
                ldsm_x4(bh0, bh1, bh2, bh3, sptr(&Kh[nr*LDQ + ncol]));
                ldsm_x4(bl0, bl1, bl2, bl3, sptr(&Kl[nr*LDQ + ncol]));
                mma_bf16(S[2*jp  ], qhf[0],qhf[1],qhf[2],qhf[3], bh0, bh1);
                mma_bf16(S[2*jp  ], qhf[0],qhf[1],qhf[2],qhf[3], bl0, bl1);
                mma_bf16(S[2*jp  ], qlf[0],qlf[1],qlf[2],qlf[3], bh0, bh1);
                mma_bf16(S[2*jp+1], qhf[0],qhf[1],qhf[2],qhf[3], bh2, bh3);
                mma_bf16(S[2*jp+1], qhf[0],qhf[1],qhf[2],qhf[3], bl2, bl3);
                mma_bf16(S[2*jp+1], qlf[0],qlf[1],qlf[2],qlf[3], bh2, bh3);
            }
        }

        #pragma unroll
        for (int j = 0; j < 8; j++) {
            uint32_t w0 = (j < 4) ? mw0.x : mw0.y;
            uint32_t w1 = (j < 4) ? mw1.x : mw1.y;
            int sh = (j & 3)*8 + 2*t;
            float e0 = __expf(S[j][0]);
            float e1 = __expf(S[j][1]);
            float e2 = __expf(S[j][2]);
            float e3 = __expf(S[j][3]);
            S[j][0] = ((w0 >> sh)     & 1u) ? e0 : 1.0f;
            S[j][1] = ((w0 >> (sh+1)) & 1u) ? e1 : 1.0f;
            S[j][2] = ((w1 >> sh)     & 1u) ? e2 : 1.0f;
            S[j][3] = ((w1 >> (sh+1)) & 1u) ? e3 : 1.0f;
            l0 += S[j][0] + S[j][1];
            l1 += S[j][2] + S[j][3];
        }

        #pragma unroll
        for (int kc = 0; kc < 4; kc++) {
            uint32_t ah[4], al[4];
            split_pack(S[2*kc  ][0], S[2*kc  ][1], ah[0], al[0]);
            split_pack(S[2*kc  ][2], S[2*kc  ][3], ah[1], al[1]);
            split_pack(S[2*kc+1][0], S[2*kc+1][1], ah[2], al[2]);
            split_pack(S[2*kc+1][2], S[2*kc+1][3], ah[3], al[3]);
            #pragma unroll
            for (int jp = 0; jp < 4; jp++) {
                int krow = kc*16 + (lane & 15);
                int ncol = 16*jp + ((lane >> 4) << 3);
                uint32_t bh0, bh1, bh2, bh3, bl0, bl1, bl2, bl3;
                ldsm_x4_trans(bh0, bh1, bh2, bh3, sptr(&Vh[krow*LDQ + ncol]));
                ldsm_x4_trans(bl0, bl1, bl2, bl3, sptr(&Vl[krow*LDQ + ncol]));
                mma_bf16(O[2*jp  ], ah[0],ah[1],ah[2],ah[3], bh0, bh1);
                mma_bf16(O[2*jp  ], ah[0],ah[1],ah[2],ah[3], bl0, bl1);
                mma_bf16(O[2*jp  ], al[0],al[1],al[2],al[3], bh0, bh1);
                mma_bf16(O[2*jp+1], ah[0],ah[1],ah[2],ah[3], bh2, bh3);
                mma_bf16(O[2*jp+1], ah[0],ah[1],ah[2],ah[3], bl2, bl3);
                mma_bf16(O[2*jp+1], al[0],al[1],al[2],al[3], bh2, bh3);
            }
        }
    }

    // ---- epilogue: reduce row sums across quad, write fp32 partials ----
    l0 += __shfl_xor_sync(0xffffffffu, l0, 1);
    l0 += __shfl_xor_sync(0xffffffffu, l0, 2);
    l1 += __shfl_xor_sync(0xffffffffu, l1, 1);
    l1 += __shfl_xor_sync(0xffffffffu, l1, 2);
    if (t == 0) {
        g_lp[(size_t)zz*BB*NH*SS + (size_t)bh*SS + rg0] = l0;
        g_lp[(size_t)zz*BB*NH*SS + (size_t)bh*SS + rg1] = l1;
    }
    float* OP = g_op + (size_t)zz*MROWS*DM;
    const size_t o0 = ((size_t)(b_*SS + rg0))*DM + h_*DH;
    const size_t o1 = ((size_t)(b_*SS + rg1))*DM + h_*DH;
    #pragma unroll
    for (int j = 0; j < 8; j++) {
        int c = j*8 + 2*t;
        float2 a0; a0.x = O[j][0]; a0.y = O[j][1];
        float2 a1; a1.x = O[j][2]; a1.y = O[j][3];
        *(float2*)&OP[o0 + c] = a0;
        *(float2*)&OP[o1 + c] = a1;
    }
}

// ============================================================
// split-KV combine: ao = (O0+O1)/(l0+l1), split to bf16 hi/lo
// ============================================================
__global__ __launch_bounds__(256)
void combine_kv() {
    size_t i4 = ((size_t)blockIdx.x * blockDim.x + threadIdx.x) * 4;
    int r = (int)(i4 / DM), c = (int)(i4 % DM);
    int b = r / SS, s = r % SS, h = c / DH;
    size_t li = (size_t)(b*NH + h)*SS + s;
    float l = g_lp[li] + g_lp[(size_t)BB*NH*SS + li];
    float inv = 1.0f / l;
    float4 p0 = *(const float4*)&g_op[i4];
    float4 p1 = *(const float4*)&g_op[(size_t)MROWS*DM + i4];
    uint32_t h0, l0, h1, l1;
    split_pack((p0.x + p1.x)*inv, (p0.y + p1.y)*inv, h0, l0);
    split_pack((p0.z + p1.z)*inv, (p0.w + p1.w)*inv, h1, l1);
    *(uint32_t*)&g_ao_h[i4]     = h0;
    *(uint32_t*)&g_ao_h[i4 + 2] = h1;
    *(uint32_t*)&g_ao_l[i4]     = l0;
    *(uint32_t*)&g_ao_l[i4 + 2] = l1;
}

// ============================================================
extern "C" void kernel_launch(void* const* d_in, const int* in_sizes, int n_in,
                              void* d_out, int out_size) {
    const float* q    = (const float*)d_in[0];
    const float* k    = (const float*)d_in[1];
    const float* v    = (const float*)d_in[2];
    const int*   msk  = (const int*)  d_in[3];
    const float* WQ_w = (const float*)d_in[4];
    const float* WQ_b = (const float*)d_in[5];
    const float* WK_w = (const float*)d_in[6];
    const float* WK_b = (const float*)d_in[7];
    const float* WV_w = (const float*)d_in[8];
    const float* WV_b = (const float*)d_in[9];
    const float* WO_w = (const float*)d_in[10];
    const float* WO_b = (const float*)d_in[11];
    float* out = (float*)d_out;

    __nv_bfloat16 *xq_h,*xq_l,*xk_h,*xk_l,*xv_h,*xv_l;
    __nv_bfloat16 *wq_h,*wq_l,*wk_h,*wk_l,*wv_h,*wv_l,*wo_h,*wo_l;
    __nv_bfloat16 *qh_h,*qh_l,*kh_h,*kh_l,*vh_h,*vh_l,*ao_h,*ao_l;
    cudaGetSymbolAddress((void**)&xq_h, g_xq_h); cudaGetSymbolAddress((void**)&xq_l, g_xq_l);
    cudaGetSymbolAddress((void**)&xk_h, g_xk_h); cudaGetSymbolAddress((void**)&xk_l, g_xk_l);
    cudaGetSymbolAddress((void**)&xv_h, g_xv_h); cudaGetSymbolAddress((void**)&xv_l, g_xv_l);
    cudaGetSymbolAddress((void**)&wq_h, g_wq_h); cudaGetSymbolAddress((void**)&wq_l, g_wq_l);
    cudaGetSymbolAddress((void**)&wk_h, g_wk_h); cudaGetSymbolAddress((void**)&wk_l, g_wk_l);
    cudaGetSymbolAddress((void**)&wv_h, g_wv_h); cudaGetSymbolAddress((void**)&wv_l, g_wv_l);
    cudaGetSymbolAddress((void**)&wo_h, g_wo_h); cudaGetSymbolAddress((void**)&wo_l, g_wo_l);
    cudaGetSymbolAddress((void**)&qh_h, g_qh_h); cudaGetSymbolAddress((void**)&qh_l, g_qh_l);
    cudaGetSymbolAddress((void**)&kh_h, g_kh_h); cudaGetSymbolAddress((void**)&kh_l, g_kh_l);
    cudaGetSymbolAddress((void**)&vh_h, g_vh_h); cudaGetSymbolAddress((void**)&vh_l, g_vh_l);
    cudaGetSymbolAddress((void**)&ao_h, g_ao_h); cudaGetSymbolAddress((void**)&ao_l, g_ao_l);

    const int flash_smem = 6 * PL * (int)sizeof(__nv_bfloat16);   // 55296 B
    cudaFuncSetAttribute(flash_attn, cudaFuncAttributeMaxDynamicSharedMemorySize, flash_smem);

    const float qscale = 1.0f / 8.0f;   // 1/sqrt(64)

    // ---- mask bit-pack ----
    {
        size_t nm = (size_t)BB*SS*SS;
        pack_mask<<<(unsigned)(nm/256), 256>>>(msk);
    }

    // ---- fused splits: inputs (3) and weights (4) ----
    const int nx = MROWS*DM, nw = DM*DM;
    {
        SplitArgs si = {};
        si.x[0] = q;    si.h[0] = xq_h; si.l[0] = xq_l;
        si.x[1] = k;    si.h[1] = xk_h; si.l[1] = xk_l;
        si.x[2] = v;    si.h[2] = xv_h; si.l[2] = xv_l;
        dim3 gi((nx/4 + 255)/256, 3);
        split_multi<<<gi, 256>>>(si, nx);

        SplitArgs sw = {};
        sw.x[0] = WQ_w; sw.h[0] = wq_h; sw.l[0] = wq_l;
        sw.x[1] = WK_w; sw.h[1] = wk_h; sw.l[1] = wk_l;
        sw.x[2] = WV_w; sw.h[2] = wv_h; sw.l[2] = wv_l;
        sw.x[3] = WO_w; sw.h[3] = wo_h; sw.l[3] = wo_l;
        dim3 gw((nw/4 + 255)/256, 4);
        split_multi<<<gw, 256>>>(sw, nw);
    }

    // ---- merged QKV projections (grid.z = 3) ----
    {
        Proj3 P;
        P.p[0] = { xq_h, xq_l, wq_h, wq_l, WQ_b, qscale, qh_h, qh_l, nullptr };
        P.p[1] = { xk_h, xk_l, wk_h, wk_l, WK_b, 1.0f,   kh_h, kh_l, nullptr };
        P.p[2] = { xv_h, xv_l, wv_h, wv_l, WV_b, 1.0f,   vh_h, vh_l, nullptr };
        dim3 pg(DM/BLK, MROWS/BLK, 3);  // (12, 64, 3)
        proj_qkv<<<pg, 128>>>(P);
    }

    // ---- fused attention, split-KV x2 ----
    dim3 fg(SS/TQ, BB*NH, KSPLIT);      // (32, 24, 2)
    flash_attn<<<fg, 128, flash_smem>>>();

    // ---- combine partials -> split bf16 ao ----
    combine_kv<<<(unsigned)((size_t)MROWS*DM/1024), 256>>>();

    // ---- output projection ----
    {
        ProjArgs A = { ao_h, ao_l, wo_h, wo_l, WO_b, 1.0f, nullptr, nullptr, out };
        dim3 pg(DM/BLK, MROWS/BLK);     // (12, 64)
        proj_out<<<pg, 128>>>(A);
    }
}

// round 17
// speedup vs baseline: 1.0490x; 1.0164x over previous
#include <cuda_runtime.h>
#include <cuda_bf16.h>
#include <cstdint>
#include <math.h>

#define BB 2
#define SS 2048
#define DM 768
#define NH 12
#define DH 64
#define MROWS (BB*SS)   // 4096
#define SW32 (SS/32)    // 64 mask words per row

#define PM 128          // proj tile M
#define PN 64           // proj tile N
#define BK  32          // proj tile K
#define SA  40          // proj smem row stride (bf16)
#define NKS (DM/BK)     // 24 k-steps
#define PA_SZ (PM*SA)   // 5120 elems
#define PB_SZ (PN*SA)   // 2560 elems
#define PROJ_SMEM ((4*PA_SZ + 4*PB_SZ) * 2)   // 61440 B

#define TQ 64           // flash q-tile rows (4 warps x 16 rows)
#define TK 64           // flash k-tile rows
#define NKT (SS/TK)     // 32 k-tiles total
#define KSPLIT 2        // split-KV factor
#define LDQ 72          // flash smem row stride (bf16)
#define PL (TQ*LDQ)     // flash plane elems

// ---- scratch (device globals; no allocation allowed) ----
__device__ __nv_bfloat16 g_xq_h[(size_t)MROWS*DM], g_xq_l[(size_t)MROWS*DM];
__device__ __nv_bfloat16 g_xk_h[(size_t)MROWS*DM], g_xk_l[(size_t)MROWS*DM];
__device__ __nv_bfloat16 g_xv_h[(size_t)MROWS*DM], g_xv_l[(size_t)MROWS*DM];
__device__ __nv_bfloat16 g_wq_h[(size_t)DM*DM], g_wq_l[(size_t)DM*DM];
__device__ __nv_bfloat16 g_wk_h[(size_t)DM*DM], g_wk_l[(size_t)DM*DM];
__device__ __nv_bfloat16 g_wv_h[(size_t)DM*DM], g_wv_l[(size_t)DM*DM];
__device__ __nv_bfloat16 g_wo_h[(size_t)DM*DM], g_wo_l[(size_t)DM*DM];
__device__ __nv_bfloat16 g_qh_h[(size_t)BB*NH*SS*DH], g_qh_l[(size_t)BB*NH*SS*DH];
__device__ __nv_bfloat16 g_kh_h[(size_t)BB*NH*SS*DH], g_kh_l[(size_t)BB*NH*SS*DH];
__device__ __nv_bfloat16 g_vh_h[(size_t)BB*NH*SS*DH], g_vh_l[(size_t)BB*NH*SS*DH];
__device__ __nv_bfloat16 g_ao_h[(size_t)MROWS*DM], g_ao_l[(size_t)MROWS*DM];
__device__ uint32_t g_mpack[(size_t)BB*SS*SW32];          // bit-packed mask
__device__ float g_op[(size_t)KSPLIT*MROWS*DM];           // split-KV partial O
__device__ float g_lp[(size_t)KSPLIT*BB*NH*SS];           // split-KV partial row sums

// ------------------------------------------------------------
// helpers
// ------------------------------------------------------------
__device__ __forceinline__ uint32_t bf2pack(__nv_bfloat16 a, __nv_bfloat16 b) {
    __nv_bfloat162 v; v.x = a; v.y = b;
    return *reinterpret_cast<uint32_t*>(&v);
}
__device__ __forceinline__ void split_pack(float x, float y, uint32_t& h, uint32_t& l) {
    __nv_bfloat16 hx = __float2bfloat16(x), hy = __float2bfloat16(y);
    h = bf2pack(hx, hy);
    l = bf2pack(__float2bfloat16(x - __bfloat162float(hx)),
                __float2bfloat16(y - __bfloat162float(hy)));
}
__device__ __forceinline__ void mma_bf16(float c[4],
                                         uint32_t a0, uint32_t a1, uint32_t a2, uint32_t a3,
                                         uint32_t b0, uint32_t b1) {
    asm volatile(
        "mma.sync.aligned.m16n8k16.row.col.f32.bf16.bf16.f32 "
        "{%0,%1,%2,%3},{%4,%5,%6,%7},{%8,%9},{%0,%1,%2,%3};"
        : "+f"(c[0]), "+f"(c[1]), "+f"(c[2]), "+f"(c[3])
        : "r"(a0), "r"(a1), "r"(a2), "r"(a3), "r"(b0), "r"(b1));
}
__device__ __forceinline__ uint32_t sptr(const void* p) {
    return (uint32_t)__cvta_generic_to_shared(p);
}
__device__ __forceinline__ void ldsm_x4(uint32_t& r0, uint32_t& r1, uint32_t& r2, uint32_t& r3, uint32_t a) {
    asm volatile("ldmatrix.sync.aligned.m8n8.x4.shared.b16 {%0,%1,%2,%3}, [%4];"
                 : "=r"(r0), "=r"(r1), "=r"(r2), "=r"(r3) : "r"(a));
}
__device__ __forceinline__ void ldsm_x4_trans(uint32_t& r0, uint32_t& r1, uint32_t& r2, uint32_t& r3, uint32_t a) {
    asm volatile("ldmatrix.sync.aligned.m8n8.x4.trans.shared.b16 {%0,%1,%2,%3}, [%4];"
                 : "=r"(r0), "=r"(r1), "=r"(r2), "=r"(r3) : "r"(a));
}
__device__ __forceinline__ void ldsm_x2(uint32_t& r0, uint32_t& r1, uint32_t a) {
    asm volatile("ldmatrix.sync.aligned.m8n8.x2.shared.b16 {%0,%1}, [%2];"
                 : "=r"(r0), "=r"(r1) : "r"(a));
}
__device__ __forceinline__ void cp16(uint32_t s, const void* g) {
    asm volatile("cp.async.cg.shared.global [%0], [%1], 16;" :: "r"(s), "l"(g));
}
__device__ __forceinline__ void cp_commit() { asm volatile("cp.async.commit_group;"); }
__device__ __forceinline__ void cp_wait0()  { asm volatile("cp.async.wait_group 0;"); }
__device__ __forceinline__ void cp_wait1()  { asm volatile("cp.async.wait_group 1;"); }

// ============================================================
// mask bit-pack: 32 ints -> 1 word via ballot
// ============================================================
__global__ __launch_bounds__(256)
void pack_mask(const int* __restrict__ M) {
    size_t i = (size_t)blockIdx.x * blockDim.x + threadIdx.x;
    uint32_t w = __ballot_sync(0xffffffffu, M[i] != 0);
    if ((threadIdx.x & 31) == 0) g_mpack[i >> 5] = w;
}

// ============================================================
// fused split: up to 4 tensors, selected by blockIdx.y
// ============================================================
struct SplitArgs {
    const float* x[4];
    __nv_bfloat16* h[4];
    __nv_bfloat16* l[4];
};

__global__ __launch_bounds__(256)
void split_multi(SplitArgs S, int n) {
    const float* x = S.x[blockIdx.y];
    __nv_bfloat16* h = S.h[blockIdx.y];
    __nv_bfloat16* l = S.l[blockIdx.y];
    int i = (blockIdx.x * blockDim.x + threadIdx.x) * 4;
    if (i >= n) return;
    float4 v = *(const float4*)&x[i];
    uint32_t h0, l0, h1, l1;
    split_pack(v.x, v.y, h0, l0);
    split_pack(v.z, v.w, h1, l1);
    uint32_t* H = (uint32_t*)h; uint32_t* L = (uint32_t*)l;
    H[(i>>1)  ] = h0; H[(i>>1)+1] = h1;
    L[(i>>1)  ] = l0; L[(i>>1)+1] = l1;
}

// ============================================================
// Projection GEMM: 128x64 tile, 256 threads (8 warps 4x2),
// double-buffered cp.async (dynamic smem 60 KB), bf16x3.
// ============================================================
struct ProjArgs {
    const __nv_bfloat16 *Agh, *Agl, *Bgh, *Bgl;
    const float* bias;
    float scale;
    __nv_bfloat16 *Oh, *Ol;   // MODE 0 outputs
    float* Of;                // MODE 1 output
};
struct Proj3 { ProjArgs p[3]; };

__device__ __forceinline__ void proj_stage(
    __nv_bfloat16* AH, __nv_bfloat16* AL, __nv_bfloat16* BH, __nv_bfloat16* BL,
    const ProjArgs& A, size_t arow0, size_t brow0, int k0, int tid) {
    const int srow = tid >> 1, scb = (tid & 1) * 16;   // A: 128 rows, 2 thr/row
    const int brow = tid >> 2, bcb = (tid & 3) * 8;    // B: 64 rows, 4 thr/row
    #pragma unroll
    for (int j = 0; j < 2; j++) {
        int c = scb + 8*j;
        cp16(sptr(&AH[srow*SA + c]), &A.Agh[(arow0+srow)*DM + k0 + c]);
        cp16(sptr(&AL[srow*SA + c]), &A.Agl[(arow0+srow)*DM + k0 + c]);
    }
    cp16(sptr(&BH[brow*SA + bcb]), &A.Bgh[(brow0+brow)*DM + k0 + bcb]);
    cp16(sptr(&BL[brow*SA + bcb]), &A.Bgl[(brow0+brow)*DM + k0 + bcb]);
}

template<int MODE>
__device__ __forceinline__ void proj_body(const ProjArgs& A) {
    extern __shared__ __nv_bfloat16 ps[];
    __nv_bfloat16* AH[2] = { ps,                       ps + PA_SZ };
    __nv_bfloat16* AL[2] = { ps + 2*PA_SZ,             ps + 3*PA_SZ };
    __nv_bfloat16* BH[2] = { ps + 4*PA_SZ,             ps + 4*PA_SZ + PB_SZ };
    __nv_bfloat16* BL[2] = { ps + 4*PA_SZ + 2*PB_SZ,   ps + 4*PA_SZ + 3*PB_SZ };

    const int tid = threadIdx.x, lane = tid & 31, warp = tid >> 5;
    const int g = lane >> 2, t = lane & 3, l15 = lane & 15;
    const int wm = warp >> 1, wn = warp & 1;     // wm 0..3, wn 0..1
    const size_t arow0 = (size_t)blockIdx.y * PM;
    const size_t brow0 = (size_t)blockIdx.x * PN;

    float acc[2][4][4] = {};

    proj_stage(AH[0], AL[0], BH[0], BL[0], A, arow0, brow0, 0, tid);
    cp_commit();

    for (int ks = 0; ks < NKS; ks++) {
        const int cur = ks & 1;
        if (ks + 1 < NKS) {
            proj_stage(AH[cur^1], AL[cur^1], BH[cur^1], BL[cur^1],
                       A, arow0, brow0, (ks+1)*BK, tid);
            cp_commit();
            cp_wait1();
        } else {
            cp_wait0();
        }
        __syncthreads();

        #pragma unroll
        for (int kc = 0; kc < BK; kc += 16) {
            uint32_t ah[2][4], al[2][4];
            #pragma unroll
            for (int i = 0; i < 2; i++) {
                int ar = wm*32 + i*16 + l15;
                int ac = kc + ((lane >> 4) << 3);
                ldsm_x4(ah[i][0], ah[i][1], ah[i][2], ah[i][3], sptr(&AH[cur][ar*SA + ac]));
                ldsm_x4(al[i][0], al[i][1], al[i][2], al[i][3], sptr(&AL[cur][ar*SA + ac]));
            }
            #pragma unroll
            for (int j = 0; j < 4; j++) {
                int br = wn*32 + j*8 + (l15 & 7);
                int bc = kc + ((l15 >> 3) << 3);
                uint32_t bh0, bh1, bl0, bl1;
                ldsm_x2(bh0, bh1, sptr(&BH[cur][br*SA + bc]));
                ldsm_x2(bl0, bl1, sptr(&BL[cur][br*SA + bc]));
                #pragma unroll
                for (int i = 0; i < 2; i++) {
                    mma_bf16(acc[i][j], ah[i][0],ah[i][1],ah[i][2],ah[i][3], bh0, bh1);
                    mma_bf16(acc[i][j], ah[i][0],ah[i][1],ah[i][2],ah[i][3], bl0, bl1);
                    mma_bf16(acc[i][j], al[i][0],al[i][1],al[i][2],al[i][3], bh0, bh1);
                }
            }
        }
        __syncthreads();   // all warps done with cur before ks+2 restages it
    }

    #pragma unroll
    for (int i = 0; i < 2; i++) {
        #pragma unroll
        for (int rr = 0; rr < 2; rr++) {
            int r = (int)arow0 + wm*32 + i*16 + g + rr*8;
            #pragma unroll
            for (int j = 0; j < 4; j++) {
                int c = (int)brow0 + wn*32 + j*8 + 2*t;
                float v0 = (acc[i][j][rr*2  ] + A.bias[c  ]) * A.scale;
                float v1 = (acc[i][j][rr*2+1] + A.bias[c+1]) * A.scale;
                if (MODE == 0) {
                    int b_ = r / SS, s_ = r % SS;
                    int h_ = c / DH, d_ = c % DH;
                    size_t idx = ((size_t)(b_*NH + h_)*SS + s_)*DH + d_;
                    uint32_t ph, pl;
                    split_pack(v0, v1, ph, pl);
                    *(uint32_t*)&A.Oh[idx] = ph;
                    *(uint32_t*)&A.Ol[idx] = pl;
                } else {
                    float2 o; o.x = v0; o.y = v1;
                    *(float2*)&A.Of[(size_t)r*DM + c] = o;
                }
            }
        }
    }
}

__global__ __launch_bounds__(256)
void proj_qkv(Proj3 P) {
    proj_body<0>(P.p[blockIdx.z]);
}

__global__ __launch_bounds__(256)
void proj_out(ProjArgs A) {
    proj_body<1>(A);
}

// ============================================================
// FLASH ATTENTION (R16-proven), split-KV x2, flat softmax.
// ============================================================
__global__ __launch_bounds__(128, 4)
void flash_attn() {
    extern __shared__ __nv_bfloat16 dsm[];
    __nv_bfloat16* Qh = dsm;
    __nv_bfloat16* Ql = dsm + PL;
    __nv_bfloat16* Kh = dsm + 2*PL;
    __nv_bfloat16* Kl = dsm + 3*PL;
    __nv_bfloat16* Vh = dsm + 4*PL;
    __nv_bfloat16* Vl = dsm + 5*PL;

    const int bh = blockIdx.y;
    const int zz = blockIdx.z;
    const int b_ = bh / NH, h_ = bh % NH;
    const int q0 = blockIdx.x * TQ;
    const size_t qoff = ((size_t)bh*SS + q0)*DH;
    const size_t koff0 = (size_t)bh*SS*DH;
    const uint32_t* MP = g_mpack + (size_t)b_*SS*SW32;

    const int tid = threadIdx.x, lane = tid & 31, warp = tid >> 5;
    const int g = lane >> 2, t = lane & 3, l15 = lane & 15;
    const int sr = tid >> 1;
    const int sc0 = (tid & 1) * 32;

    #pragma unroll
    for (int j = 0; j < 4; j++) {
        int c = sc0 + 8*j;
        cp16(sptr(&Qh[sr*LDQ + c]), &g_qh_h[qoff + (size_t)sr*DH + c]);
        cp16(sptr(&Ql[sr*LDQ + c]), &g_qh_l[qoff + (size_t)sr*DH + c]);
    }
    cp_commit();

    float O[8][4] = {};
    float l0 = 0.f, l1 = 0.f;

    const int rg0 = q0 + warp*16 + g;
    const int rg1 = rg0 + 8;

    const int kt0 = zz * (NKT/KSPLIT);
    const int kt1 = kt0 + (NKT/KSPLIT);

    for (int kt = kt0; kt < kt1; kt++) {
        __syncthreads();
        const size_t koff = koff0 + (size_t)kt*TK*DH;
        #pragma unroll
        for (int j = 0; j < 4; j++) {
            int c = sc0 + 8*j;
            cp16(sptr(&Kh[sr*LDQ + c]), &g_kh_h[koff + (size_t)sr*DH + c]);
            cp16(sptr(&Kl[sr*LDQ + c]), &g_kh_l[koff + (size_t)sr*DH + c]);
            cp16(sptr(&Vh[sr*LDQ + c]), &g_vh_h[koff + (size_t)sr*DH + c]);
            cp16(sptr(&Vl[sr*LDQ + c]), &g_vh_l[koff + (size_t)sr*DH + c]);
        }
        cp_commit();

        uint2 mw0 = *(const uint2*)&MP[(size_t)rg0*SW32 + kt*2];
        uint2 mw1 = *(const uint2*)&MP[(size_t)rg1*SW32 + kt*2];

        cp_wait0();
        __syncthreads();

        float S[8][4] = {};
        #pragma unroll
        for (int kc = 0; kc < 4; kc++) {
            uint32_t qhf[4], qlf[4];
            {
                int ar = warp*16 + l15;
                int ac = kc*16 + ((lane >> 4) << 3);
                ldsm_x4(qhf[0], qhf[1], qhf[2], qhf[3], sptr(&Qh[ar*LDQ + ac]));
                ldsm_x4(qlf[0], qlf[1], qlf[2], qlf[3], sptr(&Ql[ar*LDQ + ac]));
            }
            #pragma unroll
            for (int jp = 0; jp < 4; jp++) {
                int nr = 16*jp + ((lane >> 4) << 3) + (lane & 7);
                int ncol = kc*16 + (((lane >> 3) & 1) << 3);
                uint32_t bh0, bh1, bh2, bh3, bl0, bl1, bl2, bl3;
                ldsm_x4(bh0, bh1, bh2, bh3, sptr(&Kh[nr*LDQ + ncol]));
                ldsm_x4(bl0, bl1, bl2, bl3, sptr(&Kl[nr*LDQ + ncol]));
                mma_bf16(S[2*jp  ], qhf[0],qhf[1],qhf[2],qhf[3], bh0, bh1);
                mma_bf16(S[2*jp  ], qhf[0],qhf[1],qhf[2],qhf[3], bl0, bl1);
                mma_bf16(S[2*jp  ], qlf[0],qlf[1],qlf[2],qlf[3], bh0, bh1);
                mma_bf16(S[2*jp+1], qhf[0],qhf[1],qhf[2],qhf[3], bh2, bh3);
                mma_bf16(S[2*jp+1], qhf[0],qhf[1],qhf[2],qhf[3], bl2, bl3);
                mma_bf16(S[2*jp+1], qlf[0],qlf[1],qlf[2],qlf[3], bh2, bh3);
            }
        }

        #pragma unroll
        for (int j = 0; j < 8; j++) {
            uint32_t w0 = (j < 4) ? mw0.x : mw0.y;
            uint32_t w1 = (j < 4) ? mw1.x : mw1.y;
            int sh = (j & 3)*8 + 2*t;
            float e0 = __expf(S[j][0]);
            float e1 = __expf(S[j][1]);
            float e2 = __expf(S[j][2]);
            float e3 = __expf(S[j][3]);
            S[j][0] = ((w0 >> sh)     & 1u) ? e0 : 1.0f;
            S[j][1] = ((w0 >> (sh+1)) & 1u) ? e1 : 1.0f;
            S[j][2] = ((w1 >> sh)     & 1u) ? e2 : 1.0f;
            S[j][3] = ((w1 >> (sh+1)) & 1u) ? e3 : 1.0f;
            l0 += S[j][0] + S[j][1];
            l1 += S[j][2] + S[j][3];
        }

        #pragma unroll
        for (int kc = 0; kc < 4; kc++) {
            uint32_t ah[4], al[4];
            split_pack(S[2*kc  ][0], S[2*kc  ][1], ah[0], al[0]);
            split_pack(S[2*kc  ][2], S[2*kc  ][3], ah[1], al[1]);
            split_pack(S[2*kc+1][0], S[2*kc+1][1], ah[2], al[2]);
            split_pack(S[2*kc+1][2], S[2*kc+1][3], ah[3], al[3]);
            #pragma unroll
            for (int jp = 0; jp < 4; jp++) {
                int krow = kc*16 + (lane & 15);
                int ncol = 16*jp + ((lane >> 4) << 3);
                uint32_t bh0, bh1, bh2, bh3, bl0, bl1, bl2, bl3;
                ldsm_x4_trans(bh0, bh1, bh2, bh3, sptr(&Vh[krow*LDQ + ncol]));
                ldsm_x4_trans(bl0, bl1, bl2, bl3, sptr(&Vl[krow*LDQ + ncol]));
                mma_bf16(O[2*jp  ], ah[0],ah[1],ah[2],ah[3], bh0, bh1);
                mma_bf16(O[2*jp  ], ah[0],ah[1],ah[2],ah[3], bl0, bl1);
                mma_bf16(O[2*jp  ], al[0],al[1],al[2],al[3], bh0, bh1);
                mma_bf16(O[2*jp+1], ah[0],ah[1],ah[2],ah[3], bh2, bh3);
                mma_bf16(O[2*jp+1], ah[0],ah[1],ah[2],ah[3], bl2, bl3);
                mma_bf16(O[2*jp+1], al[0],al[1],al[2],al[3], bh2, bh3);
            }
        }
    }

    l0 += __shfl_xor_sync(0xffffffffu, l0, 1);
    l0 += __shfl_xor_sync(0xffffffffu, l0, 2);
    l1 += __shfl_xor_sync(0xffffffffu, l1, 1);
    l1 += __shfl_xor_sync(0xffffffffu, l1, 2);
    if (t == 0) {
        g_lp[(size_t)zz*BB*NH*SS + (size_t)bh*SS + rg0] = l0;
        g_lp[(size_t)zz*BB*NH*SS + (size_t)bh*SS + rg1] = l1;
    }
    float* OP = g_op + (size_t)zz*MROWS*DM;
    const size_t o0 = ((size_t)(b_*SS + rg0))*DM + h_*DH;
    const size_t o1 = ((size_t)(b_*SS + rg1))*DM + h_*DH;
    #pragma unroll
    for (int j = 0; j < 8; j++) {
        int c = j*8 + 2*t;
        float2 a0; a0.x = O[j][0]; a0.y = O[j][1];
        float2 a1; a1.x = O[j][2]; a1.y = O[j][3];
        *(float2*)&OP[o0 + c] = a0;
        *(float2*)&OP[o1 + c] = a1;
    }
}

// ============================================================
// split-KV combine: ao = (O0+O1)/(l0+l1), split to bf16 hi/lo
// ============================================================
__global__ __launch_bounds__(256)
void combine_kv() {
    size_t i4 = ((size_t)blockIdx.x * blockDim.x + threadIdx.x) * 4;
    int r = (int)(i4 / DM), c = (int)(i4 % DM);
    int b = r / SS, s = r % SS, h = c / DH;
    size_t li = (size_t)(b*NH + h)*SS + s;
    float l = g_lp[li] + g_lp[(size_t)BB*NH*SS + li];
    float inv = 1.0f / l;
    float4 p0 = *(const float4*)&g_op[i4];
    float4 p1 = *(const float4*)&g_op[(size_t)MROWS*DM + i4];
    uint32_t h0, l0, h1, l1;
    split_pack((p0.x + p1.x)*inv, (p0.y + p1.y)*inv, h0, l0);
    split_pack((p0.z + p1.z)*inv, (p0.w + p1.w)*inv, h1, l1);
    *(uint32_t*)&g_ao_h[i4]     = h0;
    *(uint32_t*)&g_ao_h[i4 + 2] = h1;
    *(uint32_t*)&g_ao_l[i4]     = l0;
    *(uint32_t*)&g_ao_l[i4 + 2] = l1;
}

// ============================================================
extern "C" void kernel_launch(void* const* d_in, const int* in_sizes, int n_in,
                              void* d_out, int out_size) {
    const float* q    = (const float*)d_in[0];
    const float* k    = (const float*)d_in[1];
    const float* v    = (const float*)d_in[2];
    const int*   msk  = (const int*)  d_in[3];
    const float* WQ_w = (const float*)d_in[4];
    const float* WQ_b = (const float*)d_in[5];
    const float* WK_w = (const float*)d_in[6];
    const float* WK_b = (const float*)d_in[7];
    const float* WV_w = (const float*)d_in[8];
    const float* WV_b = (const float*)d_in[9];
    const float* WO_w = (const float*)d_in[10];
    const float* WO_b = (const float*)d_in[11];
    float* out = (float*)d_out;

    __nv_bfloat16 *xq_h,*xq_l,*xk_h,*xk_l,*xv_h,*xv_l;
    __nv_bfloat16 *wq_h,*wq_l,*wk_h,*wk_l,*wv_h,*wv_l,*wo_h,*wo_l;
    __nv_bfloat16 *qh_h,*qh_l,*kh_h,*kh_l,*vh_h,*vh_l,*ao_h,*ao_l;
    cudaGetSymbolAddress((void**)&xq_h, g_xq_h); cudaGetSymbolAddress((void**)&xq_l, g_xq_l);
    cudaGetSymbolAddress((void**)&xk_h, g_xk_h); cudaGetSymbolAddress((void**)&xk_l, g_xk_l);
    cudaGetSymbolAddress((void**)&xv_h, g_xv_h); cudaGetSymbolAddress((void**)&xv_l, g_xv_l);
    cudaGetSymbolAddress((void**)&wq_h, g_wq_h); cudaGetSymbolAddress((void**)&wq_l, g_wq_l);
    cudaGetSymbolAddress((void**)&wk_h, g_wk_h); cudaGetSymbolAddress((void**)&wk_l, g_wk_l);
    cudaGetSymbolAddress((void**)&wv_h, g_wv_h); cudaGetSymbolAddress((void**)&wv_l, g_wv_l);
    cudaGetSymbolAddress((void**)&wo_h, g_wo_h); cudaGetSymbolAddress((void**)&wo_l, g_wo_l);
    cudaGetSymbolAddress((void**)&qh_h, g_qh_h); cudaGetSymbolAddress((void**)&qh_l, g_qh_l);
    cudaGetSymbolAddress((void**)&kh_h, g_kh_h); cudaGetSymbolAddress((void**)&kh_l, g_kh_l);
    cudaGetSymbolAddress((void**)&vh_h, g_vh_h); cudaGetSymbolAddress((void**)&vh_l, g_vh_l);
    cudaGetSymbolAddress((void**)&ao_h, g_ao_h); cudaGetSymbolAddress((void**)&ao_l, g_ao_l);

    const int flash_smem = 6 * PL * (int)sizeof(__nv_bfloat16);   // 55296 B
    cudaFuncSetAttribute(flash_attn, cudaFuncAttributeMaxDynamicSharedMemorySize, flash_smem);
    cudaFuncSetAttribute(proj_qkv, cudaFuncAttributeMaxDynamicSharedMemorySize, PROJ_SMEM);
    cudaFuncSetAttribute(proj_out, cudaFuncAttributeMaxDynamicSharedMemorySize, PROJ_SMEM);

    const float qscale = 1.0f / 8.0f;   // 1/sqrt(64)

    // ---- mask bit-pack ----
    {
        size_t nm = (size_t)BB*SS*SS;
        pack_mask<<<(unsigned)(nm/256), 256>>>(msk);
    }

    // ---- fused splits: inputs (3) and weights (4) ----
    const int nx = MROWS*DM, nw = DM*DM;
    {
        SplitArgs si = {};
        si.x[0] = q;    si.h[0] = xq_h; si.l[0] = xq_l;
        si.x[1] = k;    si.h[1] = xk_h; si.l[1] = xk_l;
        si.x[2] = v;    si.h[2] = xv_h; si.l[2] = xv_l;
        dim3 gi((nx/4 + 255)/256, 3);
        split_multi<<<gi, 256>>>(si, nx);

        SplitArgs sw = {};
        sw.x[0] = WQ_w; sw.h[0] = wq_h; sw.l[0] = wq_l;
        sw.x[1] = WK_w; sw.h[1] = wk_h; sw.l[1] = wk_l;
        sw.x[2] = WV_w; sw.h[2] = wv_h; sw.l[2] = wv_l;
        sw.x[3] = WO_w; sw.h[3] = wo_h; sw.l[3] = wo_l;
        dim3 gw((nw/4 + 255)/256, 4);
        split_multi<<<gw, 256>>>(sw, nw);
    }

    // ---- merged QKV projections (grid.z = 3), 128x64 tiles ----
    {
        Proj3 P;
        P.p[0] = { xq_h, xq_l, wq_h, wq_l, WQ_b, qscale, qh_h, qh_l, nullptr };
        P.p[1] = { xk_h, xk_l, wk_h, wk_l, WK_b, 1.0f,   kh_h, kh_l, nullptr };
        P.p[2] = { xv_h, xv_l, wv_h, wv_l, WV_b, 1.0f,   vh_h, vh_l, nullptr };
        dim3 pg(DM/PN, MROWS/PM, 3);    // (12, 32, 3)
        proj_qkv<<<pg, 256, PROJ_SMEM>>>(P);
    }

    // ---- fused attention, split-KV x2 ----
    dim3 fg(SS/TQ, BB*NH, KSPLIT);      // (32, 24, 2)
    flash_attn<<<fg, 128, flash_smem>>>();

    // ---- combine partials -> split bf16 ao ----
    combine_kv<<<(unsigned)((size_t)MROWS*DM/1024), 256>>>();

    // ---- output projection ----
    {
        ProjArgs A = { ao_h, ao_l, wo_h, wo_l, WO_b, 1.0f, nullptr, nullptr, out };
        dim3 pg(DM/PN, MROWS/PM);       // (12, 32)
        proj_out<<<pg, 256, PROJ_SMEM>>>(A);
    }
}